// round 16
// baseline (speedup 1.0000x reference)
#include <cuda_runtime.h>
#include <cuda_fp16.h>
#include <cstdint>
#include <cstddef>

#define BB 16
#define MM 16
#define JXN 128
#define JQN 64
#define DN 256

// ---------------- smem layout (byte offsets), 113536 B per CTA ---------------
constexpr int OFF_UW  = 0;        // half [72 rows][264] (w3*u; row64=w1) B of GEMM1  38016
constexpr int OFF_UR  = 38016;    // half [64 q][264 d] raw u (B of GEMM2)           33792
constexpr int OFF_AS  = 71808;    // half 2 x [128 j][40 d] A chunks (h fp16)        20480
                                  //   ALIASED post-GEMM2 by part float4[4][64]
constexpr int OFF_PH  = 92288;    // half [128 j][72 q] (P = A of GEMM2)             18432
constexpr int OFF_SU  = 110720;   // fp32 s_u[64]
constexpr int OFF_SH  = 110976;   // fp32 s_h[128]
constexpr int OFF_SPM = 111488;   // fp32 s_pm[128] (rowmax only)
constexpr int OFF_PS  = 112000;   // fp32 p_s[128]
constexpr int OFF_EX  = 112512;   // fp32 exch[2][128]
constexpr int SMEM_BYTES = 113536;

#define MMA_F16(c, a, b)                                                        \
    asm volatile(                                                               \
        "mma.sync.aligned.m16n8k16.row.col.f32.f16.f16.f32 "                    \
        "{%0,%1,%2,%3}, {%4,%5,%6,%7}, {%8,%9}, {%0,%1,%2,%3};"                 \
        : "+f"((c)[0]), "+f"((c)[1]), "+f"((c)[2]), "+f"((c)[3])                \
        : "r"((a)[0]), "r"((a)[1]), "r"((a)[2]), "r"((a)[3]),                   \
          "r"((b)[0]), "r"((b)[1]))

#define LDMATRIX_X4(r0, r1, r2, r3, addr)                                       \
    asm volatile(                                                               \
        "ldmatrix.sync.aligned.m8n8.x4.shared.b16 {%0,%1,%2,%3}, [%4];"         \
        : "=r"(r0), "=r"(r1), "=r"(r2), "=r"(r3) : "r"(addr))

#define LDMATRIX_X4_TRANS(r0, r1, r2, r3, addr)                                 \
    asm volatile(                                                               \
        "ldmatrix.sync.aligned.m8n8.x4.trans.shared.b16 {%0,%1,%2,%3}, [%4];"   \
        : "=r"(r0), "=r"(r1), "=r"(r2), "=r"(r3) : "r"(addr))

__device__ __forceinline__ uint32_t pack_h2(float a, float b) {
    __half2 h = __floats2half2_rn(a, b);
    return *(uint32_t*)&h;
}
__device__ __forceinline__ uint32_t smem_u32(const void* p) {
    uint32_t a;
    asm("{ .reg .u64 t; cvta.to.shared.u64 t, %1; cvt.u32.u64 %0, t; }" : "=r"(a) : "l"(p));
    return a;
}
#define NBAR(id, cnt)  asm volatile("bar.sync %0, %1;"   :: "r"(id), "r"(cnt) : "memory")
#define NBARR(id, cnt) asm volatile("bar.arrive %0, %1;" :: "r"(id), "r"(cnt) : "memory")

// ---------------------------------------------------------------------------
// Fused kernel: CTA = one (b,m), all 128 j rows. 256 threads, 2 CTAs/SM.
// ---------------------------------------------------------------------------
__global__ void __launch_bounds__(256, 2)
attn_h16(const float* __restrict__ hg, const float* __restrict__ ug,
         const float* __restrict__ wg, float* __restrict__ out)
{
    extern __shared__ __align__(16) char smc[];
    __half* u_w  = (__half*)(smc + OFF_UW);
    __half* u_r  = (__half*)(smc + OFF_UR);
    __half* P_h  = (__half*)(smc + OFF_PH);
    float*  s_u  = (float*)(smc + OFF_SU);
    float*  s_h  = (float*)(smc + OFF_SH);
    float*  s_pm = (float*)(smc + OFF_SPM);
    float*  p_s  = (float*)(smc + OFF_PS);
    float*  exch = (float*)(smc + OFF_EX);
    float4* part = (float4*)(smc + OFF_AS);   // alias, live after GEMM2

    const int tid  = threadIdx.x;
    const int wid  = tid >> 5;
    const int lane = tid & 31;
    const int g    = lane >> 2;
    const int t    = lane & 3;
    const int bm   = blockIdx.x;
    const int b    = bm >> 4;

    const float* __restrict__ hrow = hg + (size_t)bm * JXN * DN;
    const float* __restrict__ ub   = ug + (size_t)b * JQN * DN;
    const size_t outbase = (size_t)bm * JXN * (4 * DN);

    const int wj = wid & 3;                           // j-tile group (4 x 32 rows)
    const int wn = wid >> 2;                          // q/d tile group (2)
    const int srow = tid >> 1, sh16 = (tid & 1) * 16; // staging: row, 16-d half

    // ldmatrix lane address components (non-trans A/B)
    const int lrow  = ((lane >> 3) & 1) * 8 + (lane & 7);   // row within 16
    const int lcol  = (lane >> 4) * 8;                      // k-block 0/8
    const int brow  = (lane >> 4) * 8 + (lane & 7);         // B: row within 16
    const int bcolp = ((lane >> 3) & 1) * 8;                // B: k-block 0/8

    // ---- early prefetch of GEMM1 chunk 0 ----
    float4 ph[4];
    #pragma unroll
    for (int i = 0; i < 4; i++)
        ph[i] = *(const float4*)(hrow + srow * DN + sh16 + 4 * i);

    // ---- stage u_w (w3*u fp16) + u_r (raw u fp16), row 64 of u_w = w1 ----
    for (int idx = tid; idx < 64 * 64; idx += 256) {
        int q = idx >> 6, d4 = idx & 63;
        float4 v  = *(const float4*)(ub + q * DN + d4 * 4);
        float4 w3 = *(const float4*)(wg + 2 * DN + d4 * 4);
        *(uint2*)((char*)u_r + q * 528 + d4 * 8) =
            make_uint2(pack_h2(v.x, v.y), pack_h2(v.z, v.w));
        *(uint2*)((char*)u_w + q * 528 + d4 * 8) =
            make_uint2(pack_h2(v.x * w3.x, v.y * w3.y), pack_h2(v.z * w3.z, v.w * w3.w));
    }
    if (tid < 64) {
        float4 w1 = *(const float4*)(wg + tid * 4);
        *(uint2*)((char*)u_w + 64 * 528 + tid * 8) =
            make_uint2(pack_h2(w1.x, w1.y), pack_h2(w1.z, w1.w));
    }
    // ---- s_u[q] = u[q,:] . w2 (4 lanes per q) ----
    {
        int q = tid >> 2, sg = tid & 3;
        const float* up  = ub + q * DN + sg * 64;
        const float* w2p = wg + DN + sg * 64;
        float acc = 0.f;
        #pragma unroll 16
        for (int i = 0; i < 16; i++) {
            float4 a = *(const float4*)(up + 4 * i);
            float4 w = *(const float4*)(w2p + 4 * i);
            acc += a.x * w.x + a.y * w.y + a.z * w.z + a.w * w.w;
        }
        acc += __shfl_xor_sync(0xffffffffu, acc, 1, 4);
        acc += __shfl_xor_sync(0xffffffffu, acc, 2, 4);
        if (sg == 0) s_u[q] = acc;
    }
    __syncthreads();

    // ---- GEMM1: C1[128 j][64 q] = h . (w3*u)^T, K=256, 8 chunks, dbl-buf ----
    float c1f[2][4][4];
    #pragma unroll
    for (int mt = 0; mt < 2; mt++)
        #pragma unroll
        for (int nt = 0; nt < 4; nt++)
            #pragma unroll
            for (int i = 0; i < 4; i++) c1f[mt][nt][i] = 0.f;
    float c1x[2][4];                      // s_h column (wn==1 only)
    #pragma unroll
    for (int mt = 0; mt < 2; mt++)
        #pragma unroll
        for (int i = 0; i < 4; i++) c1x[mt][i] = 0.f;

    const uint32_t uw_base = smem_u32(u_w);
    const uint32_t boff = brow * 528 + bcolp * 2;
    const uint32_t aoff = lrow * 80 + lcol * 2;

    for (int c = 0; c < 8; c++) {
        const uint32_t As = smem_u32(smc + OFF_AS + (c & 1) * 10240);
        {   // stage A chunk: pure fp32->fp16 convert of prefetched h
            uint4 st0, st1;
            uint32_t* s0 = (uint32_t*)&st0;
            uint32_t* s1 = (uint32_t*)&st1;
            #pragma unroll
            for (int i = 0; i < 4; i++) {
                float4 x = ph[i];
                uint32_t* dstp = (i < 2) ? (s0 + 2 * i) : (s1 + 2 * (i - 2));
                dstp[0] = pack_h2(x.x, x.y);
                dstp[1] = pack_h2(x.z, x.w);
            }
            *(uint4*)((char*)smc + OFF_AS + (c & 1) * 10240 + srow * 80 + sh16 * 2)      = st0;
            *(uint4*)((char*)smc + OFF_AS + (c & 1) * 10240 + srow * 80 + sh16 * 2 + 16) = st1;
        }
        __syncthreads();
        if (c < 7) {
            #pragma unroll
            for (int i = 0; i < 4; i++)
                ph[i] = *(const float4*)(hrow + srow * DN + (c + 1) * 32 + sh16 + 4 * i);
        }
        #pragma unroll
        for (int it = 0; it < 2; it++) {
            uint32_t af[2][4];
            #pragma unroll
            for (int mt = 0; mt < 2; mt++) {
                const uint32_t addr = As + (wj * 32 + mt * 16) * 80 + it * 32 + aoff;
                LDMATRIX_X4(af[mt][0], af[mt][1], af[mt][2], af[mt][3], addr);
            }
            #pragma unroll
            for (int ntp = 0; ntp < 2; ntp++) {
                uint32_t r0, r1, r2, r3;
                const uint32_t addr = uw_base + (wn * 32 + ntp * 16) * 528
                                    + (c * 32 + it * 16) * 2 + boff;
                LDMATRIX_X4(r0, r1, r2, r3, addr);
                uint32_t bA[2] = {r0, r1}, bB[2] = {r2, r3};
                #pragma unroll
                for (int mt = 0; mt < 2; mt++) {
                    MMA_F16(c1f[mt][2 * ntp],     af[mt], bA);
                    MMA_F16(c1f[mt][2 * ntp + 1], af[mt], bB);
                }
            }
            if (wn == 1) {   // s_h column: B rows 64.. (row 64 = w1)
                uint32_t bx[2];
                bx[0] = *(const uint32_t*)((char*)u_w + (64 + g) * 528
                                           + (c * 32 + it * 16 + 2 * t) * 2);
                bx[1] = *(const uint32_t*)((char*)u_w + (64 + g) * 528
                                           + (c * 32 + it * 16 + 8 + 2 * t) * 2);
                MMA_F16(c1x[0], af[0], bx);
                MMA_F16(c1x[1], af[1], bx);
            }
        }
        // no trailing sync: next STS targets the other A buffer
    }

    // ---- s_h from MMA column 64 (wn==1, t==0 lanes own tile-col 0) ----
    if (wn == 1 && t == 0) {
        #pragma unroll
        for (int mt = 0; mt < 2; mt++) {
            s_h[wj * 32 + mt * 16 + g]     = c1x[mt][0];
            s_h[wj * 32 + mt * 16 + 8 + g] = c1x[mt][2];
        }
    }

    // ---- fragment-resident softmax over q ----
    {
        float vv[2][2][8];
        #pragma unroll
        for (int mt = 0; mt < 2; mt++)
            #pragma unroll
            for (int nt = 0; nt < 4; nt++) {
                const int q0 = wn * 32 + nt * 8 + 2 * t;
                const float su0 = s_u[q0], su1 = s_u[q0 + 1];
                vv[mt][0][2 * nt]     = c1f[mt][nt][0] + su0;
                vv[mt][0][2 * nt + 1] = c1f[mt][nt][1] + su1;
                vv[mt][1][2 * nt]     = c1f[mt][nt][2] + su0;
                vv[mt][1][2 * nt + 1] = c1f[mt][nt][3] + su1;
            }
        float mx[2][2], sm[2][2];
        #pragma unroll
        for (int mt = 0; mt < 2; mt++)
            #pragma unroll
            for (int ih = 0; ih < 2; ih++) {
                float m = vv[mt][ih][0];
                #pragma unroll
                for (int i = 1; i < 8; i++) m = fmaxf(m, vv[mt][ih][i]);
                m = fmaxf(m, __shfl_xor_sync(0xffffffffu, m, 1, 4));
                m = fmaxf(m, __shfl_xor_sync(0xffffffffu, m, 2, 4));
                mx[mt][ih] = m;
                if (t == 0) exch[wn * 128 + wj * 32 + mt * 16 + ih * 8 + g] = m;
            }
        NBAR(1 + wj, 64);
        #pragma unroll
        for (int mt = 0; mt < 2; mt++)
            #pragma unroll
            for (int ih = 0; ih < 2; ih++) {
                const int row = wj * 32 + mt * 16 + ih * 8 + g;
                mx[mt][ih] = fmaxf(mx[mt][ih], exch[(wn ^ 1) * 128 + row]);
                float s = 0.f;
                #pragma unroll
                for (int i = 0; i < 8; i++) {
                    vv[mt][ih][i] = __expf(vv[mt][ih][i] - mx[mt][ih]);
                    s += vv[mt][ih][i];
                }
                s += __shfl_xor_sync(0xffffffffu, s, 1, 4);
                s += __shfl_xor_sync(0xffffffffu, s, 2, 4);
                sm[mt][ih] = s;
            }
        NBAR(1 + wj, 64);
        #pragma unroll
        for (int mt = 0; mt < 2; mt++)
            #pragma unroll
            for (int ih = 0; ih < 2; ih++)
                if (t == 0)
                    exch[wn * 128 + wj * 32 + mt * 16 + ih * 8 + g] = sm[mt][ih];
        NBAR(1 + wj, 64);
        #pragma unroll
        for (int mt = 0; mt < 2; mt++)
            #pragma unroll
            for (int ih = 0; ih < 2; ih++) {
                const int row = wj * 32 + mt * 16 + ih * 8 + g;
                const float inv = 1.f / (sm[mt][ih] + exch[(wn ^ 1) * 128 + row]);
                #pragma unroll
                for (int nt = 0; nt < 4; nt++) {
                    *(uint32_t*)((char*)P_h + row * 144 + (wn * 32 + nt * 8 + 2 * t) * 2)
                        = pack_h2(vv[mt][ih][2 * nt] * inv, vv[mt][ih][2 * nt + 1] * inv);
                }
                if (wn == 0 && t == 0) s_pm[row] = mx[mt][ih];
            }
    }
    NBAR(1 + wj, 64);   // P rows visible within the {wj, wj+4} pair

    // ---- rendezvous: warp 0 computes p; other warps flow into GEMM2 ----
    if (wid != 0) {
        NBARR(6, 256);
    } else {
        NBAR(6, 256);
        float v0 = s_pm[lane]      + s_h[lane];
        float v1 = s_pm[lane + 32] + s_h[lane + 32];
        float v2 = s_pm[lane + 64] + s_h[lane + 64];
        float v3 = s_pm[lane + 96] + s_h[lane + 96];
        float mxp = fmaxf(fmaxf(v0, v1), fmaxf(v2, v3));
        #pragma unroll
        for (int o = 16; o >= 1; o >>= 1) mxp = fmaxf(mxp, __shfl_xor_sync(0xffffffffu, mxp, o));
        float e0 = __expf(v0 - mxp), e1 = __expf(v1 - mxp);
        float e2 = __expf(v2 - mxp), e3 = __expf(v3 - mxp);
        float s = e0 + e1 + e2 + e3;
        #pragma unroll
        for (int o = 16; o >= 1; o >>= 1) s += __shfl_xor_sync(0xffffffffu, s, o);
        float inv = 1.f / s;
        p_s[lane] = e0 * inv; p_s[lane + 32] = e1 * inv;
        p_s[lane + 64] = e2 * inv; p_s[lane + 96] = e3 * inv;
    }

    // ---- GEMM2 (barrier-free): 2 d-slabs of 128; A via ldmatrix on P_h,
    //      B via ldmatrix.trans on u_r ----
    const uint32_t ph_base = smem_u32(P_h);
    const uint32_t ur_b = smem_u32(u_r)
                        + (((lane >> 3) & 1) * 8 + (lane & 7)) * 528
                        + (lane >> 4) * 16;
    for (int s = 0; s < 2; s++) {
        float d2f[2][8][4];
        #pragma unroll
        for (int mt = 0; mt < 2; mt++)
            #pragma unroll
            for (int nt = 0; nt < 8; nt++)
                #pragma unroll
                for (int i = 0; i < 4; i++) d2f[mt][nt][i] = 0.f;

        #pragma unroll
        for (int it = 0; it < 4; it++) {
            uint32_t af[2][4];
            #pragma unroll
            for (int mt = 0; mt < 2; mt++) {
                const uint32_t addr = ph_base + (wj * 32 + mt * 16) * 144 + it * 32
                                    + lrow * 144 + lcol * 2;
                LDMATRIX_X4(af[mt][0], af[mt][1], af[mt][2], af[mt][3], addr);
            }
            #pragma unroll
            for (int ntp = 0; ntp < 4; ntp++) {
                const uint32_t addr = ur_b + it * 16 * 528
                                    + (s * 128 + wn * 64 + ntp * 16) * 2;
                uint32_t r0, r1, r2, r3;
                LDMATRIX_X4_TRANS(r0, r1, r2, r3, addr);
                uint32_t bA[2] = {r0, r1}, bB[2] = {r2, r3};
                MMA_F16(d2f[0][2 * ntp],     af[0], bA);
                MMA_F16(d2f[1][2 * ntp],     af[1], bA);
                MMA_F16(d2f[0][2 * ntp + 1], af[0], bB);
                MMA_F16(d2f[1][2 * ntp + 1], af[1], bB);
            }
        }
        // direct epilogue: segments 0,1,2
        #pragma unroll
        for (int mt = 0; mt < 2; mt++) {
            const int R0 = wj * 32 + mt * 16 + g;
            const int R1 = R0 + 8;
            float* ob0 = out + outbase + (size_t)R0 * (4 * DN);
            float* ob1 = out + outbase + (size_t)R1 * (4 * DN);
            const float* h0 = hrow + R0 * DN;
            const float* h1 = hrow + R1 * DN;
            #pragma unroll
            for (int nt = 0; nt < 8; nt++) {
                const int d = s * 128 + wn * 64 + nt * 8 + 2 * t;
                float2 hv0 = *(const float2*)(h0 + d);
                float2 hv1 = *(const float2*)(h1 + d);
                float2 ua0 = make_float2(d2f[mt][nt][0], d2f[mt][nt][1]);
                float2 ua1 = make_float2(d2f[mt][nt][2], d2f[mt][nt][3]);
                *(float2*)(ob0 + d)          = hv0;
                *(float2*)(ob0 + DN + d)     = ua0;
                *(float2*)(ob0 + 2 * DN + d) = make_float2(hv0.x * ua0.x, hv0.y * ua0.y);
                *(float2*)(ob1 + d)          = hv1;
                *(float2*)(ob1 + DN + d)     = ua1;
                *(float2*)(ob1 + 2 * DN + d) = make_float2(hv1.x * ua1.x, hv1.y * ua1.y);
            }
        }
    }
    __syncthreads();   // p_s visible; A_s region free for part alias

    // ---- h_att = sum_j p_j h[j,:]; write segment 3 ----
    {
        const int jg = tid >> 6, dq = tid & 63;
        float4 acc = make_float4(0.f, 0.f, 0.f, 0.f);
        #pragma unroll 4
        for (int j = jg * 32; j < jg * 32 + 32; j++) {
            float4 hv = *(const float4*)(hrow + j * DN + dq * 4);
            float pj = p_s[j];
            acc.x += pj * hv.x; acc.y += pj * hv.y; acc.z += pj * hv.z; acc.w += pj * hv.w;
        }
        part[jg * 64 + dq] = acc;
        __syncthreads();
        if (tid < 64) {
            float4 sacc = part[tid];
            #pragma unroll
            for (int gg = 1; gg < 4; gg++) {
                float4 v = part[gg * 64 + tid];
                sacc.x += v.x; sacc.y += v.y; sacc.z += v.z; sacc.w += v.w;
            }
            part[tid] = sacc;
        }
        __syncthreads();
        const float4 ha = part[dq];
        #pragma unroll 4
        for (int j = jg * 32; j < jg * 32 + 32; j++) {
            float4 hv = *(const float4*)(hrow + j * DN + dq * 4);
            float4 o3;
            o3.x = hv.x * ha.x; o3.y = hv.y * ha.y; o3.z = hv.z * ha.z; o3.w = hv.w * ha.w;
            *(float4*)(out + outbase + (size_t)j * (4 * DN) + 3 * DN + dq * 4) = o3;
        }
    }
}

// ---------------------------------------------------------------------------
extern "C" void kernel_launch(void* const* d_in, const int* in_sizes, int n_in,
                              void* d_out, int out_size)
{
    (void)in_sizes; (void)n_in; (void)out_size;
    const float* h = (const float*)d_in[0];
    const float* u = (const float*)d_in[1];
    const float* w = (const float*)d_in[2];
    // d_in[3] (scalar bias b) cancels in both softmaxes -> unused.
    float* out = (float*)d_out;

    cudaFuncSetAttribute(attn_h16, cudaFuncAttributeMaxDynamicSharedMemorySize, SMEM_BYTES);
    attn_h16<<<BB * MM, 256, SMEM_BYTES>>>(h, u, w, out);
}

// round 17
// speedup vs baseline: 1.0750x; 1.0750x over previous
#include <cuda_runtime.h>
#include <cuda_fp16.h>
#include <cstdint>
#include <cstddef>

#define BB 16
#define MM 16
#define JXN 128
#define JQN 64
#define DN 256

// ---------------- smem layout (byte offsets), 62208 B per CTA ----------------
constexpr int OFF_UH  = 0;        // half [64 q][264 d] (B of GEMM1 + GEMM2) 33792
constexpr int OFF_PH  = 33792;    // half [128 j][72 q] (P = A of GEMM2)     18432
constexpr int OFF_W   = 52224;    // fp32 w1|w2|w3 (3072)
constexpr int OFF_SU  = 55296;    // fp32 s_u[64]
constexpr int OFF_SH  = 55552;    // fp32 s_h[128]
constexpr int OFF_SPM = 56064;    // fp32 s_pm[128] (rowmax only)
constexpr int OFF_PS  = 56576;    // fp32 p_s[128]
constexpr int OFF_EX  = 57088;    // fp32 exch[2][128]
constexpr int OFF_PART= 58112;    // float4 part[4][64] = 4096
constexpr int SMEM_BYTES = 62208;

#define MMA_F16(c, a, b)                                                        \
    asm volatile(                                                               \
        "mma.sync.aligned.m16n8k16.row.col.f32.f16.f16.f32 "                    \
        "{%0,%1,%2,%3}, {%4,%5,%6,%7}, {%8,%9}, {%0,%1,%2,%3};"                 \
        : "+f"((c)[0]), "+f"((c)[1]), "+f"((c)[2]), "+f"((c)[3])                \
        : "r"((a)[0]), "r"((a)[1]), "r"((a)[2]), "r"((a)[3]),                   \
          "r"((b)[0]), "r"((b)[1]))

#define LDMATRIX_X4_TRANS(r0, r1, r2, r3, addr)                                 \
    asm volatile(                                                               \
        "ldmatrix.sync.aligned.m8n8.x4.trans.shared.b16 {%0,%1,%2,%3}, [%4];"   \
        : "=r"(r0), "=r"(r1), "=r"(r2), "=r"(r3) : "r"(addr))

__device__ __forceinline__ uint32_t pack_h2(float a, float b) {
    __half2 h = __floats2half2_rn(a, b);
    return *(uint32_t*)&h;
}
__device__ __forceinline__ uint32_t smem_u32(const void* p) {
    uint32_t a;
    asm("{ .reg .u64 t; cvta.to.shared.u64 t, %1; cvt.u32.u64 %0, t; }" : "=r"(a) : "l"(p));
    return a;
}
#define NBAR(id, cnt)  asm volatile("bar.sync %0, %1;"   :: "r"(id), "r"(cnt) : "memory")
#define NBARR(id, cnt) asm volatile("bar.arrive %0, %1;" :: "r"(id), "r"(cnt) : "memory")

// ---------------------------------------------------------------------------
// Fused kernel: CTA = one (b,m), all 128 j rows. 256 threads, 2 CTAs/SM.
// GEMM1 is barrier-free: A fragments loaded straight from gmem h (fp32),
// scaled by w3 in fp32, packed to fp16 in registers.
// ---------------------------------------------------------------------------
__global__ void __launch_bounds__(256, 2)
attn_h16(const float* __restrict__ hg, const float* __restrict__ ug,
         const float* __restrict__ wg, float* __restrict__ out)
{
    extern __shared__ __align__(16) char smc[];
    __half* u_h  = (__half*)(smc + OFF_UH);
    __half* P_h  = (__half*)(smc + OFF_PH);
    float*  wsm  = (float*)(smc + OFF_W);
    float*  s_u  = (float*)(smc + OFF_SU);
    float*  s_h  = (float*)(smc + OFF_SH);
    float*  s_pm = (float*)(smc + OFF_SPM);
    float*  p_s  = (float*)(smc + OFF_PS);
    float*  exch = (float*)(smc + OFF_EX);
    float4* part = (float4*)(smc + OFF_PART);

    const int tid  = threadIdx.x;
    const int wid  = tid >> 5;
    const int lane = tid & 31;
    const int g    = lane >> 2;
    const int t    = lane & 3;
    const int bm   = blockIdx.x;
    const int b    = bm >> 4;

    const float* __restrict__ hrow = hg + (size_t)bm * JXN * DN;
    const float* __restrict__ ub   = ug + (size_t)b * JQN * DN;
    const size_t outbase = (size_t)bm * JXN * (4 * DN);

    const int wj = wid & 3;                          // j-tile group (4 x 32 rows)
    const int wn = wid >> 2;                         // q/d tile group (2)

    // ---- stage w; u_h [q][264] fp16 ----
    for (int i = tid; i < 3 * DN; i += 256) wsm[i] = wg[i];
    for (int idx = tid; idx < 64 * 64; idx += 256) {
        int q = idx >> 6, d4 = idx & 63;
        float4 v = *(const float4*)(ub + q * DN + d4 * 4);
        *(uint2*)((char*)u_h + q * 528 + d4 * 8) =
            make_uint2(pack_h2(v.x, v.y), pack_h2(v.z, v.w));
    }
    // ---- s_u[q] = u[q,:] . w2 (4 lanes per q) ----
    {
        int q = tid >> 2, sg = tid & 3;
        const float* up  = ub + q * DN + sg * 64;
        const float* w2p = wg + DN + sg * 64;
        float acc = 0.f;
        #pragma unroll 16
        for (int i = 0; i < 16; i++) {
            float4 a = *(const float4*)(up + 4 * i);
            float4 w = *(const float4*)(w2p + 4 * i);
            acc += a.x * w.x + a.y * w.y + a.z * w.z + a.w * w.w;
        }
        acc += __shfl_xor_sync(0xffffffffu, acc, 1, 4);
        acc += __shfl_xor_sync(0xffffffffu, acc, 2, 4);
        if (sg == 0) s_u[q] = acc;
    }
    __syncthreads();   // the ONLY pre-GEMM1 barrier

    // ---- GEMM1 (barrier-free): C1[128 j][64 q] = (h*w3).u^T, K=256 ----
    float c1f[2][4][4];
    #pragma unroll
    for (int mt = 0; mt < 2; mt++)
        #pragma unroll
        for (int nt = 0; nt < 4; nt++)
            #pragma unroll
            for (int i = 0; i < 4; i++) c1f[mt][nt][i] = 0.f;
    float sh0[2] = {0.f, 0.f}, sh1[2] = {0.f, 0.f};

    const float* __restrict__ hA0 = hrow + (wj * 32 + g) * DN + 2 * t;       // mt=0 row
    const float* __restrict__ hA1 = hA0 + 16 * DN;                           // mt=1 row

    #pragma unroll 2
    for (int c = 0; c < 8; c++) {
        #pragma unroll
        for (int it = 0; it < 2; it++) {
            const int kb = c * 32 + it * 16;
            const float2 w3a = *(const float2*)(wsm + 2 * DN + kb + 2 * t);
            const float2 w3b = *(const float2*)(wsm + 2 * DN + kb + 8 + 2 * t);
            uint32_t af[2][4];
            #pragma unroll
            for (int mt = 0; mt < 2; mt++) {
                const float* h0 = (mt == 0 ? hA0 : hA1) + kb;
                const float* h1 = h0 + 8 * DN;
                float2 x0 = *(const float2*)h0;
                float2 x1 = *(const float2*)h1;
                float2 x2 = *(const float2*)(h0 + 8);
                float2 x3 = *(const float2*)(h1 + 8);
                if (wn == 0) {
                    const float2 w1a = *(const float2*)(wsm + kb + 2 * t);
                    const float2 w1b = *(const float2*)(wsm + kb + 8 + 2 * t);
                    sh0[mt] += x0.x * w1a.x + x0.y * w1a.y + x2.x * w1b.x + x2.y * w1b.y;
                    sh1[mt] += x1.x * w1a.x + x1.y * w1a.y + x3.x * w1b.x + x3.y * w1b.y;
                }
                af[mt][0] = pack_h2(x0.x * w3a.x, x0.y * w3a.y);
                af[mt][1] = pack_h2(x1.x * w3a.x, x1.y * w3a.y);
                af[mt][2] = pack_h2(x2.x * w3b.x, x2.y * w3b.y);
                af[mt][3] = pack_h2(x3.x * w3b.x, x3.y * w3b.y);
            }
            #pragma unroll
            for (int nt = 0; nt < 4; nt++) {
                const __half* bp = u_h + (wn * 32 + nt * 8 + g) * 264 + kb + 2 * t;
                uint32_t bf[2];
                bf[0] = *(const uint32_t*)bp;
                bf[1] = *(const uint32_t*)(bp + 8);
                MMA_F16(c1f[0][nt], af[0], bf);
                MMA_F16(c1f[1][nt], af[1], bf);
            }
        }
    }

    // ---- s_h reduce (wn==0 warps own it) ----
    if (wn == 0) {
        #pragma unroll
        for (int mt = 0; mt < 2; mt++) {
            float a = sh0[mt], bv = sh1[mt];
            a  += __shfl_xor_sync(0xffffffffu, a, 1, 4);
            a  += __shfl_xor_sync(0xffffffffu, a, 2, 4);
            bv += __shfl_xor_sync(0xffffffffu, bv, 1, 4);
            bv += __shfl_xor_sync(0xffffffffu, bv, 2, 4);
            if (t == 0) {
                s_h[wj * 32 + mt * 16 + g]     = a;
                s_h[wj * 32 + mt * 16 + 8 + g] = bv;
            }
        }
    }

    // ---- fragment-resident softmax over q ----
    {
        float vv[2][2][8];
        #pragma unroll
        for (int mt = 0; mt < 2; mt++)
            #pragma unroll
            for (int nt = 0; nt < 4; nt++) {
                const int q0 = wn * 32 + nt * 8 + 2 * t;
                const float su0 = s_u[q0], su1 = s_u[q0 + 1];
                vv[mt][0][2 * nt]     = c1f[mt][nt][0] + su0;
                vv[mt][0][2 * nt + 1] = c1f[mt][nt][1] + su1;
                vv[mt][1][2 * nt]     = c1f[mt][nt][2] + su0;
                vv[mt][1][2 * nt + 1] = c1f[mt][nt][3] + su1;
            }
        float mx[2][2], sm[2][2];
        #pragma unroll
        for (int mt = 0; mt < 2; mt++)
            #pragma unroll
            for (int ih = 0; ih < 2; ih++) {
                float m = vv[mt][ih][0];
                #pragma unroll
                for (int i = 1; i < 8; i++) m = fmaxf(m, vv[mt][ih][i]);
                m = fmaxf(m, __shfl_xor_sync(0xffffffffu, m, 1, 4));
                m = fmaxf(m, __shfl_xor_sync(0xffffffffu, m, 2, 4));
                mx[mt][ih] = m;
                if (t == 0) exch[wn * 128 + wj * 32 + mt * 16 + ih * 8 + g] = m;
            }
        NBAR(1 + wj, 64);
        #pragma unroll
        for (int mt = 0; mt < 2; mt++)
            #pragma unroll
            for (int ih = 0; ih < 2; ih++) {
                const int row = wj * 32 + mt * 16 + ih * 8 + g;
                mx[mt][ih] = fmaxf(mx[mt][ih], exch[(wn ^ 1) * 128 + row]);
                float s = 0.f;
                #pragma unroll
                for (int i = 0; i < 8; i++) {
                    vv[mt][ih][i] = __expf(vv[mt][ih][i] - mx[mt][ih]);
                    s += vv[mt][ih][i];
                }
                s += __shfl_xor_sync(0xffffffffu, s, 1, 4);
                s += __shfl_xor_sync(0xffffffffu, s, 2, 4);
                sm[mt][ih] = s;
            }
        NBAR(1 + wj, 64);
        #pragma unroll
        for (int mt = 0; mt < 2; mt++)
            #pragma unroll
            for (int ih = 0; ih < 2; ih++)
                if (t == 0)
                    exch[wn * 128 + wj * 32 + mt * 16 + ih * 8 + g] = sm[mt][ih];
        NBAR(1 + wj, 64);
        #pragma unroll
        for (int mt = 0; mt < 2; mt++)
            #pragma unroll
            for (int ih = 0; ih < 2; ih++) {
                const int row = wj * 32 + mt * 16 + ih * 8 + g;
                const float inv = 1.f / (sm[mt][ih] + exch[(wn ^ 1) * 128 + row]);
                #pragma unroll
                for (int nt = 0; nt < 4; nt++) {
                    *(uint32_t*)((char*)P_h + row * 144 + (wn * 32 + nt * 8 + 2 * t) * 2)
                        = pack_h2(vv[mt][ih][2 * nt] * inv, vv[mt][ih][2 * nt + 1] * inv);
                }
                if (wn == 0 && t == 0) s_pm[row] = mx[mt][ih];
            }
    }
    NBAR(1 + wj, 64);   // P rows visible within the {wj, wj+4} pair

    // ---- rendezvous: warp 0 computes p; other warps flow into GEMM2 ----
    if (wid != 0) {
        NBARR(6, 256);
    } else {
        NBAR(6, 256);
        float v0 = s_pm[lane]      + s_h[lane];
        float v1 = s_pm[lane + 32] + s_h[lane + 32];
        float v2 = s_pm[lane + 64] + s_h[lane + 64];
        float v3 = s_pm[lane + 96] + s_h[lane + 96];
        float mxp = fmaxf(fmaxf(v0, v1), fmaxf(v2, v3));
        #pragma unroll
        for (int o = 16; o >= 1; o >>= 1) mxp = fmaxf(mxp, __shfl_xor_sync(0xffffffffu, mxp, o));
        float e0 = __expf(v0 - mxp), e1 = __expf(v1 - mxp);
        float e2 = __expf(v2 - mxp), e3 = __expf(v3 - mxp);
        float s = e0 + e1 + e2 + e3;
        #pragma unroll
        for (int o = 16; o >= 1; o >>= 1) s += __shfl_xor_sync(0xffffffffu, s, o);
        float inv = 1.f / s;
        p_s[lane] = e0 * inv; p_s[lane + 32] = e1 * inv;
        p_s[lane + 64] = e2 * inv; p_s[lane + 96] = e3 * inv;
    }

    // ---- GEMM2 (barrier-free): 2 d-slabs of 128; B via ldmatrix.trans on u_h --
    const uint32_t uh_b = smem_u32(u_h)
                        + (((lane >> 3) & 1) * 8 + (lane & 7)) * 528
                        + (lane >> 4) * 16;
    for (int s = 0; s < 2; s++) {
        float d2f[2][8][4];
        #pragma unroll
        for (int mt = 0; mt < 2; mt++)
            #pragma unroll
            for (int nt = 0; nt < 8; nt++)
                #pragma unroll
                for (int i = 0; i < 4; i++) d2f[mt][nt][i] = 0.f;

        #pragma unroll
        for (int it = 0; it < 4; it++) {
            const int kb = it * 16;
            uint32_t af[2][4];
            #pragma unroll
            for (int mt = 0; mt < 2; mt++) {
                const __half* ap = P_h + (wj * 32 + mt * 16 + g) * 72 + kb + 2 * t;
                af[mt][0] = *(const uint32_t*)ap;
                af[mt][1] = *(const uint32_t*)(ap + 8 * 72);
                af[mt][2] = *(const uint32_t*)(ap + 8);
                af[mt][3] = *(const uint32_t*)(ap + 8 * 72 + 8);
            }
            #pragma unroll
            for (int ntp = 0; ntp < 4; ntp++) {
                const uint32_t addr = uh_b + it * 16 * 528
                                    + (s * 128 + wn * 64 + ntp * 16) * 2;
                uint32_t r0, r1, r2, r3;
                LDMATRIX_X4_TRANS(r0, r1, r2, r3, addr);
                uint32_t bA[2] = {r0, r1}, bB[2] = {r2, r3};
                MMA_F16(d2f[0][2 * ntp],     af[0], bA);
                MMA_F16(d2f[1][2 * ntp],     af[1], bA);
                MMA_F16(d2f[0][2 * ntp + 1], af[0], bB);
                MMA_F16(d2f[1][2 * ntp + 1], af[1], bB);
            }
        }
        // direct epilogue: segments 0,1,2
        #pragma unroll
        for (int mt = 0; mt < 2; mt++) {
            const int R0 = wj * 32 + mt * 16 + g;
            const int R1 = R0 + 8;
            float* ob0 = out + outbase + (size_t)R0 * (4 * DN);
            float* ob1 = out + outbase + (size_t)R1 * (4 * DN);
            const float* h0 = hrow + R0 * DN;
            const float* h1 = hrow + R1 * DN;
            #pragma unroll
            for (int nt = 0; nt < 8; nt++) {
                const int d = s * 128 + wn * 64 + nt * 8 + 2 * t;
                float2 hv0 = *(const float2*)(h0 + d);
                float2 hv1 = *(const float2*)(h1 + d);
                float2 ua0 = make_float2(d2f[mt][nt][0], d2f[mt][nt][1]);
                float2 ua1 = make_float2(d2f[mt][nt][2], d2f[mt][nt][3]);
                *(float2*)(ob0 + d)          = hv0;
                *(float2*)(ob0 + DN + d)     = ua0;
                *(float2*)(ob0 + 2 * DN + d) = make_float2(hv0.x * ua0.x, hv0.y * ua0.y);
                *(float2*)(ob1 + d)          = hv1;
                *(float2*)(ob1 + DN + d)     = ua1;
                *(float2*)(ob1 + 2 * DN + d) = make_float2(hv1.x * ua1.x, hv1.y * ua1.y);
            }
        }
    }
    __syncthreads();   // p_s visible to all warps

    // ---- h_att = sum_j p_j h[j,:]; write segment 3 ----
    {
        const int jg = tid >> 6, dq = tid & 63;
        float4 acc = make_float4(0.f, 0.f, 0.f, 0.f);
        #pragma unroll 4
        for (int j = jg * 32; j < jg * 32 + 32; j++) {
            float4 hv = *(const float4*)(hrow + j * DN + dq * 4);
            float pj = p_s[j];
            acc.x += pj * hv.x; acc.y += pj * hv.y; acc.z += pj * hv.z; acc.w += pj * hv.w;
        }
        part[jg * 64 + dq] = acc;
        __syncthreads();
        if (tid < 64) {
            float4 sacc = part[tid];
            #pragma unroll
            for (int gg = 1; gg < 4; gg++) {
                float4 v = part[gg * 64 + tid];
                sacc.x += v.x; sacc.y += v.y; sacc.z += v.z; sacc.w += v.w;
            }
            part[tid] = sacc;
        }
        __syncthreads();
        const float4 ha = part[dq];
        #pragma unroll 4
        for (int j = jg * 32; j < jg * 32 + 32; j++) {
            float4 hv = *(const float4*)(hrow + j * DN + dq * 4);
            float4 o3;
            o3.x = hv.x * ha.x; o3.y = hv.y * ha.y; o3.z = hv.z * ha.z; o3.w = hv.w * ha.w;
            *(float4*)(out + outbase + (size_t)j * (4 * DN) + 3 * DN + dq * 4) = o3;
        }
    }
}

// ---------------------------------------------------------------------------
extern "C" void kernel_launch(void* const* d_in, const int* in_sizes, int n_in,
                              void* d_out, int out_size)
{
    (void)in_sizes; (void)n_in; (void)out_size;
    const float* h = (const float*)d_in[0];
    const float* u = (const float*)d_in[1];
    const float* w = (const float*)d_in[2];
    // d_in[3] (scalar bias b) cancels in both softmaxes -> unused.
    float* out = (float*)d_out;

    cudaFuncSetAttribute(attn_h16, cudaFuncAttributeMaxDynamicSharedMemorySize, SMEM_BYTES);
    attn_h16<<<BB * MM, 256, SMEM_BYTES>>>(h, u, w, out);
}